// round 1
// baseline (speedup 1.0000x reference)
#include <cuda_runtime.h>

#define VOCAB 32000
#define BATCH 4
#define SEQ   2048
#define NVEC  (VOCAB / 4)   // 8000 float4 per row

// Scratch histogram (allocation-free rule: __device__ global)
__device__ int g_hist[BATCH * VOCAB];

__global__ void zero_hist_kernel() {
    int i = blockIdx.x * blockDim.x + threadIdx.x;
    if (i < BATCH * VOCAB) g_hist[i] = 0;
}

// One CTA per (b, s) row: argmax over VOCAB, then atomicAdd into histogram.
__global__ __launch_bounds__(256, 8)
void argmax_hist_kernel(const float* __restrict__ logits) {
    const int row = blockIdx.x;                       // 0 .. B*S-1
    const float4* __restrict__ p =
        reinterpret_cast<const float4*>(logits + (size_t)row * VOCAB);

    float best = -3.402823466e+38f;
    int   bidx = 0;
    const int tid = threadIdx.x;

    // Strided float4 scan. Sequential in-thread compares use strict '>' so the
    // first (lowest-index) occurrence of the max wins within a thread.
    #pragma unroll 4
    for (int i = tid; i < NVEC; i += 256) {
        float4 v = p[i];
        int base = i << 2;
        if (v.x > best) { best = v.x; bidx = base;     }
        if (v.y > best) { best = v.y; bidx = base + 1; }
        if (v.z > best) { best = v.z; bidx = base + 2; }
        if (v.w > best) { best = v.w; bidx = base + 3; }
    }

    // Warp reduction (tie -> smaller index, matching jnp.argmax first-hit)
    #pragma unroll
    for (int off = 16; off > 0; off >>= 1) {
        float ov = __shfl_down_sync(0xFFFFFFFFu, best, off);
        int   oi = __shfl_down_sync(0xFFFFFFFFu, bidx, off);
        if (ov > best || (ov == best && oi < bidx)) { best = ov; bidx = oi; }
    }

    __shared__ float s_val[8];
    __shared__ int   s_idx[8];
    const int wid = tid >> 5;
    const int lid = tid & 31;
    if (lid == 0) { s_val[wid] = best; s_idx[wid] = bidx; }
    __syncthreads();

    if (wid == 0) {
        best = (lid < 8) ? s_val[lid] : -3.402823466e+38f;
        bidx = (lid < 8) ? s_idx[lid] : 0x7FFFFFFF;
        #pragma unroll
        for (int off = 4; off > 0; off >>= 1) {
            float ov = __shfl_down_sync(0xFFFFFFFFu, best, off);
            int   oi = __shfl_down_sync(0xFFFFFFFFu, bidx, off);
            if (ov > best || (ov == best && oi < bidx)) { best = ov; bidx = oi; }
        }
        if (lid == 0) {
            int b = row / SEQ;
            atomicAdd(&g_hist[b * VOCAB + bidx], 1);
        }
    }
}

// out[b, v] = (v is special) ? 0 : min(hist, 4) / 4
__global__ void finalize_kernel(float* __restrict__ out) {
    int i = blockIdx.x * blockDim.x + threadIdx.x;
    if (i < BATCH * VOCAB) {
        int v = i % VOCAB;
        float h = fminf((float)g_hist[i], 4.0f) * 0.25f;
        out[i] = (v <= 2) ? 0.0f : h;   // PAD=0, START=1, END=2
    }
}

extern "C" void kernel_launch(void* const* d_in, const int* in_sizes, int n_in,
                              void* d_out, int out_size) {
    const float* logits = (const float*)d_in[0];
    float* out = (float*)d_out;

    zero_hist_kernel<<<(BATCH * VOCAB + 255) / 256, 256>>>();
    argmax_hist_kernel<<<BATCH * SEQ, 256>>>(logits);
    finalize_kernel<<<(BATCH * VOCAB + 255) / 256, 256>>>(out);
}

// round 2
// speedup vs baseline: 1.0371x; 1.0371x over previous
#include <cuda_runtime.h>

#define VOCAB 32000
#define BATCH 4
#define SEQ   2048
#define NVEC  (VOCAB / 4)   // 8000 float4 per row

// Scratch histogram. Zero-initialized at module load; finalize_kernel resets
// it to zero after consuming it, so it is zero at every argmax entry
// (correctness run and every graph replay) — no separate zeroing launch.
__device__ int g_hist[BATCH * VOCAB];

// One CTA per (b, s) row: argmax over VOCAB, then atomicAdd into histogram.
__global__ __launch_bounds__(256, 8)
void argmax_hist_kernel(const float* __restrict__ logits) {
    const int row = blockIdx.x;                       // 0 .. B*S-1
    const float4* __restrict__ p =
        reinterpret_cast<const float4*>(logits + (size_t)row * VOCAB);

    float best = -3.402823466e+38f;
    int   bidx = 0;
    const int tid = threadIdx.x;

    // Strided float4 scan, streaming (evict-first) loads. Sequential
    // in-thread compares use strict '>' so the first (lowest-index)
    // occurrence of the max wins within a thread.
    #pragma unroll 4
    for (int i = tid; i < NVEC; i += 256) {
        float4 v = __ldcs(p + i);
        int base = i << 2;
        if (v.x > best) { best = v.x; bidx = base;     }
        if (v.y > best) { best = v.y; bidx = base + 1; }
        if (v.z > best) { best = v.z; bidx = base + 2; }
        if (v.w > best) { best = v.w; bidx = base + 3; }
    }

    // Warp reduction (tie -> smaller index, matching jnp.argmax first-hit)
    #pragma unroll
    for (int off = 16; off > 0; off >>= 1) {
        float ov = __shfl_down_sync(0xFFFFFFFFu, best, off);
        int   oi = __shfl_down_sync(0xFFFFFFFFu, bidx, off);
        if (ov > best || (ov == best && oi < bidx)) { best = ov; bidx = oi; }
    }

    __shared__ float s_val[8];
    __shared__ int   s_idx[8];
    const int wid = tid >> 5;
    const int lid = tid & 31;
    if (lid == 0) { s_val[wid] = best; s_idx[wid] = bidx; }
    __syncthreads();

    if (wid == 0) {
        best = (lid < 8) ? s_val[lid] : -3.402823466e+38f;
        bidx = (lid < 8) ? s_idx[lid] : 0x7FFFFFFF;
        #pragma unroll
        for (int off = 4; off > 0; off >>= 1) {
            float ov = __shfl_down_sync(0xFFFFFFFFu, best, off);
            int   oi = __shfl_down_sync(0xFFFFFFFFu, bidx, off);
            if (ov > best || (ov == best && oi < bidx)) { best = ov; bidx = oi; }
        }
        if (lid == 0) {
            int b = row / SEQ;
            atomicAdd(&g_hist[b * VOCAB + bidx], 1);
        }
    }
}

// out[b, v] = (v is special) ? 0 : min(hist, 4) / 4 ; also resets g_hist to 0
// so the next kernel_launch (graph replay) sees a clean histogram.
__global__ void finalize_kernel(float* __restrict__ out) {
    const int i = blockIdx.x * blockDim.x + threadIdx.x;   // int4 index
    const int N4 = (BATCH * VOCAB) / 4;
    if (i < N4) {
        int4* hp = reinterpret_cast<int4*>(g_hist) + i;
        int4 h = *hp;
        *hp = make_int4(0, 0, 0, 0);

        const int e0 = i << 2;
        const int v0 = e0 % VOCAB;   // VOCAB % 4 == 0 -> whole int4 in one row

        float4 o;
        o.x = (v0     <= 2) ? 0.0f : fminf((float)h.x, 4.0f) * 0.25f;
        o.y = (v0 + 1 <= 2) ? 0.0f : fminf((float)h.y, 4.0f) * 0.25f;
        o.z = (v0 + 2 <= 2) ? 0.0f : fminf((float)h.z, 4.0f) * 0.25f;
        o.w = (v0 + 3 <= 2) ? 0.0f : fminf((float)h.w, 4.0f) * 0.25f;
        reinterpret_cast<float4*>(out)[i] = o;
    }
}

extern "C" void kernel_launch(void* const* d_in, const int* in_sizes, int n_in,
                              void* d_out, int out_size) {
    const float* logits = (const float*)d_in[0];
    float* out = (float*)d_out;

    argmax_hist_kernel<<<BATCH * SEQ, 256>>>(logits);
    finalize_kernel<<<((BATCH * VOCAB / 4) + 255) / 256, 256>>>(out);
}